// round 2
// baseline (speedup 1.0000x reference)
#include <cuda_runtime.h>
#include <math.h>

#define BATCH   16
#define DMODEL  4096
#define NH      32
#define NKV     8
#define DK      128
#define GQ      4          // NH / NKV
#define MAXBLK  256
#define SPLITS  8
#define TT      64         // tokens per attention tile

typedef unsigned long long u64;

// packed fp32x2 FMA / MUL (sm_100+): zero-cost pairing of adjacent regs
#define FMA2(acc, w, x) asm("fma.rn.f32x2 %0, %1, %2, %0;" : "+l"(acc) : "l"(w), "l"(x))
#define MUL2(d, a, b)   asm("mul.rn.f32x2 %0, %1, %2;"     : "=l"(d)  : "l"(a), "l"(b))

// ---------------- scratch (static device globals; no allocation) ------------
__device__ float g_q  [BATCH * DMODEL];          // Q after proj+rope
__device__ float g_k  [BATCH * NKV * DK];        // new K after rope
__device__ float g_v  [BATCH * NKV * DK];        // new V
__device__ float g_att[BATCH * DMODEL];          // attention output (pre W_O)
__device__ float g_po [BATCH * NKV * SPLITS * GQ * DK];
__device__ float g_pm [BATCH * NKV * SPLITS * GQ];
__device__ float g_pl [BATCH * NKV * SPLITS * GQ];

// ============ fused QKV projection + RoPE ====================================
// grid = 384 blocks, 256 threads (8 warps). Each warp computes one (rlo, rhi)
// row PAIR for all 16 batches using packed f32x2 accumulation, then applies
// RoPE in-register (rhi = rlo + 64 within the head for Q/K).
__global__ __launch_bounds__(256) void gemv_qkv(
    const float* __restrict__ WQ, const float* __restrict__ WK,
    const float* __restrict__ WV, const float* __restrict__ x,
    const int* __restrict__ positions)
{
    __shared__ __align__(16) float xs[BATCH][512];
    const int tid  = threadIdx.x;
    const int lane = tid & 31;
    const int wid  = tid >> 5;
    const int pair = blockIdx.x * 8 + wid;

    const float* W; float* outp; int ld, lp; bool rope;
    if (pair < 2048)      { W = WQ; outp = g_q; ld = DMODEL; rope = true;  lp = pair; }
    else if (pair < 2560) { W = WK; outp = g_k; ld = 1024;   rope = true;  lp = pair - 2048; }
    else                  { W = WV; outp = g_v; ld = 1024;   rope = false; lp = pair - 2560; }
    const int head = lp >> 6, d = lp & 63;
    const int rlo = head * 128 + d, rhi = rlo + 64;
    const float* wlo = W + (size_t)rlo * DMODEL;
    const float* whi = W + (size_t)rhi * DMODEL;

    u64 accA[16], accB[16];
#pragma unroll
    for (int b = 0; b < 16; b++) { accA[b] = 0ull; accB[b] = 0ull; }

    const float4* xg  = (const float4*)x;
    float4*       xs4 = (float4*)&xs[0][0];

    for (int t = 0; t < DMODEL; t += 512) {
        __syncthreads();
#pragma unroll
        for (int i = 0; i < 8; i++) {
            int f  = tid + i * 256;
            int b  = f >> 7;
            int kk = f & 127;
            xs4[f] = xg[b * (DMODEL / 4) + (t >> 2) + kk];
        }
        __syncthreads();
#pragma unroll
        for (int it = 0; it < 4; it++) {
            int k = t + it * 128 + lane * 4;
            ulonglong2 wa = *(const ulonglong2*)(wlo + k);
            ulonglong2 wb = *(const ulonglong2*)(whi + k);
#pragma unroll
            for (int b = 0; b < 16; b++) {
                ulonglong2 xv = *(const ulonglong2*)&xs[b][it * 128 + lane * 4];
                FMA2(accA[b], wa.x, xv.x);
                FMA2(accA[b], wa.y, xv.y);
                FMA2(accB[b], wb.x, xv.x);
                FMA2(accB[b], wb.y, xv.y);
            }
        }
    }
    float rA[16], rB[16];
#pragma unroll
    for (int b = 0; b < 16; b++) {
        float2 fa = *(float2*)&accA[b];
        float2 fb = *(float2*)&accB[b];
        rA[b] = fa.x + fa.y;
        rB[b] = fb.x + fb.y;
#pragma unroll
        for (int off = 16; off; off >>= 1) {
            rA[b] += __shfl_xor_sync(0xffffffffu, rA[b], off);
            rB[b] += __shfl_xor_sync(0xffffffffu, rB[b], off);
        }
    }
    if (lane == 0) {
        if (rope) {
            float inv = exp2f(-(float)d * 0.2076205059304601f);  // log2(1e4)/64
#pragma unroll
            for (int b = 0; b < 16; b++) {
                float s, c;
                sincosf((float)positions[b] * inv, &s, &c);
                outp[(size_t)b * ld + rlo] = rA[b] * c - rB[b] * s;
                outp[(size_t)b * ld + rhi] = rB[b] * c + rA[b] * s;
            }
        } else {
#pragma unroll
            for (int b = 0; b < 16; b++) {
                outp[(size_t)b * ld + rlo] = rA[b];
                outp[(size_t)b * ld + rhi] = rB[b];
            }
        }
    }
}

// ============ W_O projection (pair rows 2p, 2p+1; no rope) ===================
__global__ __launch_bounds__(256) void gemv_o(const float* __restrict__ W,
                                              const float* __restrict__ x,
                                              float* __restrict__ out)
{
    __shared__ __align__(16) float xs[BATCH][512];
    const int tid  = threadIdx.x;
    const int lane = tid & 31;
    const int wid  = tid >> 5;
    const int pair = blockIdx.x * 8 + wid;
    const int rlo = pair * 2, rhi = rlo + 1;
    const float* wlo = W + (size_t)rlo * DMODEL;
    const float* whi = W + (size_t)rhi * DMODEL;

    u64 accA[16], accB[16];
#pragma unroll
    for (int b = 0; b < 16; b++) { accA[b] = 0ull; accB[b] = 0ull; }

    const float4* xg  = (const float4*)x;
    float4*       xs4 = (float4*)&xs[0][0];

    for (int t = 0; t < DMODEL; t += 512) {
        __syncthreads();
#pragma unroll
        for (int i = 0; i < 8; i++) {
            int f  = tid + i * 256;
            int b  = f >> 7;
            int kk = f & 127;
            xs4[f] = xg[b * (DMODEL / 4) + (t >> 2) + kk];
        }
        __syncthreads();
#pragma unroll
        for (int it = 0; it < 4; it++) {
            int k = t + it * 128 + lane * 4;
            ulonglong2 wa = *(const ulonglong2*)(wlo + k);
            ulonglong2 wb = *(const ulonglong2*)(whi + k);
#pragma unroll
            for (int b = 0; b < 16; b++) {
                ulonglong2 xv = *(const ulonglong2*)&xs[b][it * 128 + lane * 4];
                FMA2(accA[b], wa.x, xv.x);
                FMA2(accA[b], wa.y, xv.y);
                FMA2(accB[b], wb.x, xv.x);
                FMA2(accB[b], wb.y, xv.y);
            }
        }
    }
    float rA[16], rB[16];
#pragma unroll
    for (int b = 0; b < 16; b++) {
        float2 fa = *(float2*)&accA[b];
        float2 fb = *(float2*)&accB[b];
        rA[b] = fa.x + fa.y;
        rB[b] = fb.x + fb.y;
#pragma unroll
        for (int off = 16; off; off >>= 1) {
            rA[b] += __shfl_xor_sync(0xffffffffu, rA[b], off);
            rB[b] += __shfl_xor_sync(0xffffffffu, rB[b], off);
        }
    }
    if (lane == 0) {
#pragma unroll
        for (int b = 0; b < 16; b++) {
            out[(size_t)b * DMODEL + rlo] = rA[b];
            out[(size_t)b * DMODEL + rhi] = rB[b];
        }
    }
}

// ============ flash-decode attention, split over sequence ====================
// grid = (SPLITS, NKV, BATCH), block = 256
__global__ __launch_bounds__(256) void attn_kernel(
    const float* __restrict__ k_pool, const float* __restrict__ v_pool,
    const int* __restrict__ positions, const int* __restrict__ block_table)
{
    __shared__ __align__(16) float Vs[TT][DK];
    __shared__ float  ss [GQ][TT];
    __shared__ __align__(8) float2 psd[GQ][TT];   // duplicated probs for f32x2
    __shared__ float  salpha[GQ];
    __shared__ __align__(16) float qs[GQ * DK];

    const int split = blockIdx.x, h = blockIdx.y, b = blockIdx.z;
    const int tid = threadIdx.x, lane = tid & 31, wid = tid >> 5;

    const int pos = positions[b];
    const int seq = pos + 1;
    const int chunk = (seq + SPLITS - 1) / SPLITS;
    const int s0 = split * chunk;
    const int s1 = min(s0 + chunk, seq);

    qs[tid]       = g_q[b * DMODEL + h * GQ * DK + tid];
    qs[tid + 256] = g_q[b * DMODEL + h * GQ * DK + tid + 256];
    __syncthreads();

    // hoisted q registers (per-lane slice of all 4 group heads)
    const float4 q0 = *(const float4*)&qs[0 * DK + lane * 4];
    const float4 q1 = *(const float4*)&qs[1 * DK + lane * 4];
    const float4 q2 = *(const float4*)&qs[2 * DK + lane * 4];
    const float4 q3 = *(const float4*)&qs[3 * DK + lane * 4];

    const float scale = 0.08838834764831845f;  // 1/sqrt(128)
    float m_run = -INFINITY, l_run = 0.f;
    const int g2 = tid >> 6;
    const int d0 = (tid & 63) * 2;
    u64 o2 = 0ull;                               // packed (o0, o1)

    const int jb = wid * 8;

    for (int t0 = s0; t0 < s1; t0 += TT) {
        const int nv = min(s1 - t0, TT);

        // ---- phase A0: batched page lookups (8 independent table LDGs) ----
        long off[8];
#pragma unroll
        for (int jj = 0; jj < 8; jj++) {
            int j = jb + jj, gt = t0 + j;
            long o = -1;
            if (j < nv) {
                if (gt == pos) o = -2;
                else {
                    int page = block_table[b * MAXBLK + (gt >> 4)];
                    o = (((long)page * 16 + (gt & 15)) * NKV + h) * DK;
                }
            }
            off[jj] = o;
        }
        // ---- phase A1: batched K/V loads (MLP = 16) ----
        float4 kreg[8], vreg[8];
#pragma unroll
        for (int jj = 0; jj < 8; jj++) {
            long o = off[jj];
            if (o >= 0) {
                kreg[jj] = *(const float4*)(k_pool + o + lane * 4);
                vreg[jj] = *(const float4*)(v_pool + o + lane * 4);
            } else if (o == -2) {
                kreg[jj] = *(const float4*)(g_k + (b * NKV + h) * DK + lane * 4);
                vreg[jj] = *(const float4*)(g_v + (b * NKV + h) * DK + lane * 4);
            } else {
                kreg[jj] = make_float4(0.f, 0.f, 0.f, 0.f);
                vreg[jj] = make_float4(0.f, 0.f, 0.f, 0.f);
            }
        }
        // ---- phase A2: scores + stage V ----
#pragma unroll
        for (int jj = 0; jj < 8; jj++) {
            int j = jb + jj;
            if (j < nv) {
                *(float4*)&Vs[j][lane * 4] = vreg[jj];
                float4 kv = kreg[jj];
                float p0 = kv.x * q0.x + kv.y * q0.y + kv.z * q0.z + kv.w * q0.w;
                float p1 = kv.x * q1.x + kv.y * q1.y + kv.z * q1.z + kv.w * q1.w;
                float p2 = kv.x * q2.x + kv.y * q2.y + kv.z * q2.z + kv.w * q2.w;
                float p3 = kv.x * q3.x + kv.y * q3.y + kv.z * q3.z + kv.w * q3.w;
#pragma unroll
                for (int offv = 16; offv; offv >>= 1) {
                    p0 += __shfl_xor_sync(0xffffffffu, p0, offv);
                    p1 += __shfl_xor_sync(0xffffffffu, p1, offv);
                    p2 += __shfl_xor_sync(0xffffffffu, p2, offv);
                    p3 += __shfl_xor_sync(0xffffffffu, p3, offv);
                }
                if (lane == 0) {
                    ss[0][j] = p0 * scale;
                    ss[1][j] = p1 * scale;
                    ss[2][j] = p2 * scale;
                    ss[3][j] = p3 * scale;
                }
            }
        }
        __syncthreads();
        // ---- phase B1: online softmax (warps 0..3, one per g) ----
        if (wid < 4) {
            int g = wid;
            float v0 = (lane      < nv) ? ss[g][lane]      : -INFINITY;
            float v1 = (lane + 32 < nv) ? ss[g][lane + 32] : -INFINITY;
            float mt = fmaxf(v0, v1);
#pragma unroll
            for (int offv = 16; offv; offv >>= 1)
                mt = fmaxf(mt, __shfl_xor_sync(0xffffffffu, mt, offv));
            float m_new = fmaxf(m_run, mt);
            float alpha = __expf(m_run - m_new);
            float e0 = __expf(v0 - m_new);
            float e1 = __expf(v1 - m_new);
            psd[g][lane]      = make_float2(e0, e0);
            psd[g][lane + 32] = make_float2(e1, e1);
            float sum = e0 + e1;
#pragma unroll
            for (int offv = 16; offv; offv >>= 1)
                sum += __shfl_xor_sync(0xffffffffu, sum, offv);
            l_run = l_run * alpha + sum;
            m_run = m_new;
            if (lane == 0) salpha[g] = alpha;
        }
        __syncthreads();
        // ---- phase B2: packed O accumulation ----
        {
            float a = salpha[g2];
            float2 ad = make_float2(a, a);
            u64 a2 = *(u64*)&ad;
            u64 t;
            MUL2(t, o2, a2);
            o2 = t;
#pragma unroll 4
            for (int j = 0; j < nv; j++) {
                u64 v = *(const u64*)&Vs[j][d0];
                u64 p = *(const u64*)&psd[g2][j];
                FMA2(o2, p, v);
            }
        }
        __syncthreads();
    }

    const int pidx = (b * NKV + h) * SPLITS + split;
    float2 of = *(float2*)&o2;
    g_po[pidx * (GQ * DK) + g2 * DK + d0]     = of.x;
    g_po[pidx * (GQ * DK) + g2 * DK + d0 + 1] = of.y;
    if (wid < 4 && lane == 0) {
        g_pm[pidx * GQ + wid] = m_run;
        g_pl[pidx * GQ + wid] = l_run;
    }
}

// ---------------- combine split partials -> g_att ---------------------------
__global__ void combine_kernel()
{
    int h = blockIdx.x & (NKV - 1);
    int b = blockIdx.x / NKV;
    int d = threadIdx.x;
    int base = (b * NKV + h) * SPLITS;
    for (int g = 0; g < GQ; g++) {
        float M = -INFINITY;
#pragma unroll
        for (int s = 0; s < SPLITS; s++)
            M = fmaxf(M, g_pm[(base + s) * GQ + g]);
        float L = 0.f, o = 0.f;
#pragma unroll
        for (int s = 0; s < SPLITS; s++) {
            float e = expf(g_pm[(base + s) * GQ + g] - M);
            L += g_pl[(base + s) * GQ + g] * e;
            o += e * g_po[(base + s) * (GQ * DK) + g * DK + d];
        }
        g_att[b * DMODEL + (h * GQ + g) * DK + d] = o / L;
    }
}

// ---------------- host launcher ---------------------------------------------
extern "C" void kernel_launch(void* const* d_in, const int* in_sizes, int n_in,
                              void* d_out, int out_size)
{
    const float* hs = (const float*)d_in[0];
    const float* WQ = (const float*)d_in[1];
    const float* WK = (const float*)d_in[2];
    const float* WV = (const float*)d_in[3];
    const float* WO = (const float*)d_in[4];
    const float* kp = (const float*)d_in[5];
    const float* vp = (const float*)d_in[6];
    const int*   ps = (const int*)d_in[7];
    const int*   bt = (const int*)d_in[8];
    float* out = (float*)d_out;

    float* gatt;
    cudaGetSymbolAddress((void**)&gatt, g_att);

    gemv_qkv<<<384, 256>>>(WQ, WK, WV, hs, ps);
    attn_kernel<<<dim3(SPLITS, NKV, BATCH), 256>>>(kp, vp, ps, bt);
    combine_kernel<<<BATCH * NKV, 128>>>();
    gemv_o<<<256, 256>>>(WO, gatt, out);
}

// round 3
// speedup vs baseline: 1.6215x; 1.6215x over previous
#include <cuda_runtime.h>
#include <math.h>

#define BATCH   16
#define DMODEL  4096
#define NH      32
#define NKV     8
#define DK      128
#define GQ      4
#define MAXBLK  256
#define SPLITS  8
#define TT      64
#define KSPLIT  4
#define KT      64
#define ROWS_QKV 6144
#define ROWS_O   4096

typedef unsigned long long u64;

#define FMA2(acc, w, x) asm("fma.rn.f32x2 %0, %1, %2, %0;" : "+l"(acc) : "l"(w), "l"(x))
#define MUL2(d, a, b)   asm("mul.rn.f32x2 %0, %1, %2;"     : "=l"(d)  : "l"(a), "l"(b))
#define CP16(dst, src)  asm volatile("cp.async.cg.shared.global [%0], [%1], 16;" :: "r"(dst), "l"(src))
#define CPCOMMIT()      asm volatile("cp.async.commit_group;")
#define CPWAIT(n)       asm volatile("cp.async.wait_group %0;" :: "n"(n))

__device__ __forceinline__ unsigned sptr(const void* p) {
    return (unsigned)__cvta_generic_to_shared(p);
}

// ---------------- scratch ----------------------------------------------------
__device__ float g_q  [BATCH * DMODEL];
__device__ float g_k  [BATCH * NKV * DK];
__device__ float g_v  [BATCH * NKV * DK];
__device__ float g_att[BATCH * DMODEL];
__device__ float g_po [BATCH * NKV * SPLITS * GQ * DK];
__device__ float g_pm [BATCH * NKV * SPLITS * GQ];
__device__ float g_pl [BATCH * NKV * SPLITS * GQ];
__device__ float g_part_qkv[KSPLIT * ROWS_QKV * BATCH];
__device__ float g_part_o  [KSPLIT * ROWS_O   * BATCH];

// ============ GEMM: 64 rows/CTA x 16 batches, k-split, f32x2 =================
// 128 threads = 4 warps; warp owns 16 rows. lane = (i = lane>>4, b = lane&15).
// Lane accumulates 8 row-pairs (rows 2j+i) for batch b. Weights double-buffered
// via cp.async; x tile staged too. Partial dot (k-range 1024) -> part buffer.
__global__ __launch_bounds__(128, 4) void gemm_k(
    const float* __restrict__ WQ, const float* __restrict__ WK,
    const float* __restrict__ WV, const float* __restrict__ x,
    float* __restrict__ part, int rows_total)
{
    __shared__ __align__(16) float ws[2][64][68];
    __shared__ __align__(16) float xs[2][16][68];

    const int tid  = threadIdx.x;
    const int lane = tid & 31;
    const int wid  = tid >> 5;
    const int rowBase = blockIdx.x * 64;
    const int k0      = blockIdx.y * (DMODEL / KSPLIT);

    const float* W; int wr;
    if (rowBase < 4096)      { W = WQ; wr = rowBase; }
    else if (rowBase < 5120) { W = WK; wr = rowBase - 4096; }
    else                     { W = WV; wr = rowBase - 5120; }

    const unsigned wsA = sptr(&ws[0][0][0]);
    const unsigned xsA = sptr(&xs[0][0][0]);

    const int wrow_t = tid >> 4;        // 0..7
    const int wcol_t = (tid & 15) * 4;  // 0..60
    const float* wsrc0 = W + (size_t)wr * DMODEL + k0 + wcol_t;

    // issue chunk c into buffer buf
    #define ISSUE(c, buf) do {                                                 \
        const float* wp = wsrc0 + (size_t)(c) * KT;                            \
        _Pragma("unroll")                                                      \
        for (int s = 0; s < 8; s++) {                                          \
            int r = wrow_t + s * 8;                                            \
            CP16(wsA + (((buf) * 64 + r) * 68 + wcol_t) * 4,                   \
                 wp + (size_t)r * DMODEL);                                     \
        }                                                                      \
        _Pragma("unroll")                                                      \
        for (int s = 0; s < 2; s++) {                                          \
            int idx = tid + s * 128;                                           \
            int bb = idx >> 4, kq = (idx & 15) * 4;                            \
            CP16(xsA + (((buf) * 16 + bb) * 68 + kq) * 4,                      \
                 x + (size_t)bb * DMODEL + k0 + (c) * KT + kq);                \
        }                                                                      \
        CPCOMMIT();                                                            \
    } while (0)

    u64 acc[8];
#pragma unroll
    for (int j = 0; j < 8; j++) acc[j] = 0ull;

    const int i = lane >> 4;
    const int b = lane & 15;
    const int NC = (DMODEL / KSPLIT) / KT;   // 16

    ISSUE(0, 0);
    for (int c = 0; c < NC; c++) {
        if (c + 1 < NC) { ISSUE(c + 1, (c + 1) & 1); CPWAIT(1); }
        else            { CPWAIT(0); }
        __syncthreads();
        const int buf = c & 1;
        const float* wrow0 = &ws[buf][wid * 16 + i][0];
        const float* xrow  = &xs[buf][b][0];
#pragma unroll
        for (int k4 = 0; k4 < KT; k4 += 4) {
            ulonglong2 xv = *(const ulonglong2*)(xrow + k4);
#pragma unroll
            for (int j = 0; j < 8; j++) {
                ulonglong2 wv = *(const ulonglong2*)(wrow0 + (2 * j) * 68 + k4);
                FMA2(acc[j], wv.x, xv.x);
                FMA2(acc[j], wv.y, xv.y);
            }
        }
        __syncthreads();
    }
#pragma unroll
    for (int j = 0; j < 8; j++) {
        int row = rowBase + wid * 16 + 2 * j + i;
        float2 f = *(float2*)&acc[j];
        part[((size_t)blockIdx.y * rows_total + row) * BATCH + b] = f.x + f.y;
    }
    #undef ISSUE
}

// ============ reduce QKV partials + RoPE =====================================
// items: Q pairs 32768, K pairs 8192, V elems 16384  -> 57344 / 256 = 224 blk
__global__ void reduce_qkv(const int* __restrict__ positions)
{
    int id = blockIdx.x * 256 + threadIdx.x;
    if (id < 40960) {                       // rotation pairs (Q then K)
        int isK  = id >= 32768;
        int lid  = isK ? id - 32768 : id;
        int b    = lid & 15;
        int d    = (lid >> 4) & 63;
        int head = lid >> 10;
        int rowlo = (isK ? 4096 : 0) + head * 128 + d;
        float lo = 0.f, hi = 0.f;
#pragma unroll
        for (int s = 0; s < KSPLIT; s++) {
            lo += g_part_qkv[(s * ROWS_QKV + rowlo)      * BATCH + b];
            hi += g_part_qkv[(s * ROWS_QKV + rowlo + 64) * BATCH + b];
        }
        float inv = exp2f(-(float)d * 0.2076205059304601f);  // log2(1e4)/64
        float sn, cs;
        sincosf((float)positions[b] * inv, &sn, &cs);
        float r0 = lo * cs - hi * sn;
        float r1 = hi * cs + lo * sn;
        if (!isK) {
            g_q[b * DMODEL + head * 128 + d]      = r0;
            g_q[b * DMODEL + head * 128 + d + 64] = r1;
        } else {
            g_k[b * 1024 + head * 128 + d]      = r0;
            g_k[b * 1024 + head * 128 + d + 64] = r1;
        }
    } else {                                // V rows (no rope)
        int lid = id - 40960;
        int b = lid & 15;
        int r = lid >> 4;
        float v = 0.f;
#pragma unroll
        for (int s = 0; s < KSPLIT; s++)
            v += g_part_qkv[(s * ROWS_QKV + 5120 + r) * BATCH + b];
        g_v[b * 1024 + r] = v;
    }
}

// ============ reduce O partials -> d_out =====================================
__global__ void reduce_o(float* __restrict__ out)
{
    int id = blockIdx.x * 256 + threadIdx.x;   // 65536
    int b = id & 15;
    int r = id >> 4;
    float v = 0.f;
#pragma unroll
    for (int s = 0; s < KSPLIT; s++)
        v += g_part_o[(s * ROWS_O + r) * BATCH + b];
    out[(size_t)b * DMODEL + r] = v;
}

// ============ flash-decode attention =========================================
__global__ __launch_bounds__(256, 2) void attn_kernel(
    const float* __restrict__ k_pool, const float* __restrict__ v_pool,
    const int* __restrict__ positions, const int* __restrict__ block_table)
{
    __shared__ __align__(16) float Vs[TT][DK];
    __shared__ float  ss [GQ][TT];
    __shared__ __align__(8) float2 psd[GQ][TT];
    __shared__ float  salpha[GQ];
    __shared__ __align__(16) float qs[GQ * DK];

    const int split = blockIdx.x, h = blockIdx.y, b = blockIdx.z;
    const int tid = threadIdx.x, lane = tid & 31, wid = tid >> 5;

    const int pos = positions[b];
    const int seq = pos + 1;
    const int chunk = (seq + SPLITS - 1) / SPLITS;
    const int s0 = split * chunk;
    const int s1 = min(s0 + chunk, seq);

    qs[tid]       = g_q[b * DMODEL + h * GQ * DK + tid];
    qs[tid + 256] = g_q[b * DMODEL + h * GQ * DK + tid + 256];
    __syncthreads();

    const float4 q0 = *(const float4*)&qs[0 * DK + lane * 4];
    const float4 q1 = *(const float4*)&qs[1 * DK + lane * 4];
    const float4 q2 = *(const float4*)&qs[2 * DK + lane * 4];
    const float4 q3 = *(const float4*)&qs[3 * DK + lane * 4];

    const unsigned VsA = sptr(&Vs[0][0]);
    const float scale = 0.08838834764831845f;
    float m_run = -INFINITY, l_run = 0.f;
    const int g2 = tid >> 6;
    const int d0 = (tid & 63) * 2;
    u64 o2 = 0ull;
    const int jb = wid * 8;

    for (int t0 = s0; t0 < s1; t0 += TT) {
        const int nv = min(s1 - t0, TT);

        int off[8];
#pragma unroll
        for (int jj = 0; jj < 8; jj++) {
            int j = jb + jj, gt = t0 + j;
            int o = -1;
            if (j < nv) {
                if (gt == pos) o = -2;
                else {
                    int page = block_table[b * MAXBLK + (gt >> 4)];
                    o = ((page * 16 + (gt & 15)) * NKV + h) * DK;
                }
            }
            off[jj] = o;
        }
        float4 kreg[8];
#pragma unroll
        for (int jj = 0; jj < 8; jj++) {
            int o = off[jj], j = jb + jj;
            if (o != -1) {
                const float* kp2 = (o == -2) ? g_k + (b * NKV + h) * DK : k_pool + (size_t)o;
                const float* vp2 = (o == -2) ? g_v + (b * NKV + h) * DK : v_pool + (size_t)o;
                kreg[jj] = *(const float4*)(kp2 + lane * 4);
                CP16(VsA + (j * DK + lane * 4) * 4, vp2 + lane * 4);
            }
        }
        CPCOMMIT();
#pragma unroll
        for (int jj = 0; jj < 8; jj++) {
            int j = jb + jj;
            if (j < nv) {
                float4 kv = kreg[jj];
                float p0 = kv.x * q0.x + kv.y * q0.y + kv.z * q0.z + kv.w * q0.w;
                float p1 = kv.x * q1.x + kv.y * q1.y + kv.z * q1.z + kv.w * q1.w;
                float p2 = kv.x * q2.x + kv.y * q2.y + kv.z * q2.z + kv.w * q2.w;
                float p3 = kv.x * q3.x + kv.y * q3.y + kv.z * q3.z + kv.w * q3.w;
#pragma unroll
                for (int offv = 16; offv; offv >>= 1) {
                    p0 += __shfl_xor_sync(0xffffffffu, p0, offv);
                    p1 += __shfl_xor_sync(0xffffffffu, p1, offv);
                    p2 += __shfl_xor_sync(0xffffffffu, p2, offv);
                    p3 += __shfl_xor_sync(0xffffffffu, p3, offv);
                }
                if (lane == 0) {
                    ss[0][j] = p0 * scale;
                    ss[1][j] = p1 * scale;
                    ss[2][j] = p2 * scale;
                    ss[3][j] = p3 * scale;
                }
            }
        }
        CPWAIT(0);
        __syncthreads();
        if (wid < 4) {
            int g = wid;
            float v0 = (lane      < nv) ? ss[g][lane]      : -INFINITY;
            float v1 = (lane + 32 < nv) ? ss[g][lane + 32] : -INFINITY;
            float mt = fmaxf(v0, v1);
#pragma unroll
            for (int offv = 16; offv; offv >>= 1)
                mt = fmaxf(mt, __shfl_xor_sync(0xffffffffu, mt, offv));
            float m_new = fmaxf(m_run, mt);
            float alpha = __expf(m_run - m_new);
            float e0 = __expf(v0 - m_new);
            float e1 = __expf(v1 - m_new);
            psd[g][lane]      = make_float2(e0, e0);
            psd[g][lane + 32] = make_float2(e1, e1);
            float sum = e0 + e1;
#pragma unroll
            for (int offv = 16; offv; offv >>= 1)
                sum += __shfl_xor_sync(0xffffffffu, sum, offv);
            l_run = l_run * alpha + sum;
            m_run = m_new;
            if (lane == 0) salpha[g] = alpha;
        }
        __syncthreads();
        {
            float a = salpha[g2];
            float2 ad = make_float2(a, a);
            u64 a2 = *(u64*)&ad;
            u64 t;
            MUL2(t, o2, a2);
            o2 = t;
#pragma unroll 4
            for (int j = 0; j < nv; j++) {
                u64 v = *(const u64*)&Vs[j][d0];
                u64 p = *(const u64*)&psd[g2][j];
                FMA2(o2, p, v);
            }
        }
        __syncthreads();
    }

    const int pidx = (b * NKV + h) * SPLITS + split;
    float2 of = *(float2*)&o2;
    g_po[pidx * (GQ * DK) + g2 * DK + d0]     = of.x;
    g_po[pidx * (GQ * DK) + g2 * DK + d0 + 1] = of.y;
    if (wid < 4 && lane == 0) {
        g_pm[pidx * GQ + wid] = m_run;
        g_pl[pidx * GQ + wid] = l_run;
    }
}

// ---------------- combine split partials -> g_att ---------------------------
__global__ void combine_kernel()
{
    int h = blockIdx.x & (NKV - 1);
    int b = blockIdx.x / NKV;
    int d = threadIdx.x;
    int base = (b * NKV + h) * SPLITS;
    for (int g = 0; g < GQ; g++) {
        float M = -INFINITY;
#pragma unroll
        for (int s = 0; s < SPLITS; s++)
            M = fmaxf(M, g_pm[(base + s) * GQ + g]);
        float L = 0.f, o = 0.f;
#pragma unroll
        for (int s = 0; s < SPLITS; s++) {
            float e = expf(g_pm[(base + s) * GQ + g] - M);
            L += g_pl[(base + s) * GQ + g] * e;
            o += e * g_po[(base + s) * (GQ * DK) + g * DK + d];
        }
        g_att[b * DMODEL + (h * GQ + g) * DK + d] = o / L;
    }
}

// ---------------- host launcher ---------------------------------------------
extern "C" void kernel_launch(void* const* d_in, const int* in_sizes, int n_in,
                              void* d_out, int out_size)
{
    const float* hs = (const float*)d_in[0];
    const float* WQ = (const float*)d_in[1];
    const float* WK = (const float*)d_in[2];
    const float* WV = (const float*)d_in[3];
    const float* WO = (const float*)d_in[4];
    const float* kp = (const float*)d_in[5];
    const float* vp = (const float*)d_in[6];
    const int*   ps = (const int*)d_in[7];
    const int*   bt = (const int*)d_in[8];
    float* out = (float*)d_out;

    float *gatt, *partQ, *partO;
    cudaGetSymbolAddress((void**)&gatt,  g_att);
    cudaGetSymbolAddress((void**)&partQ, g_part_qkv);
    cudaGetSymbolAddress((void**)&partO, g_part_o);

    gemm_k<<<dim3(ROWS_QKV / 64, KSPLIT), 128>>>(WQ, WK, WV, hs, partQ, ROWS_QKV);
    reduce_qkv<<<224, 256>>>(ps);
    attn_kernel<<<dim3(SPLITS, NKV, BATCH), 256>>>(kp, vp, ps, bt);
    combine_kernel<<<BATCH * NKV, 128>>>();
    gemm_k<<<dim3(ROWS_O / 64, KSPLIT), 128>>>(WO, WO, WO, gatt, partO, ROWS_O);
    reduce_o<<<256, 256>>>(out);
}